// round 17
// baseline (speedup 1.0000x reference)
#include <cuda_runtime.h>
#include <cstddef>

#define TT 1024
#define BB 8
#define VV 32000
#define EE 32
#define HH 8
#define NROWS (TT*BB)      // 8192
#define VBLK  25           // v-blocks (bx)
#define VITER 10           // outer iters; per iter a warp covers 8 tile-pairs = 128 v
#define LOG2E 1.4426950408889634f
#define LN2   0.6931471805599453f

#define NCARRIER 16
#define ABASE    16
#define NA       400        // A-blocks: 25 bx x 16 groups (4 cohorts each)
#define BBASE    416
#define NB       1600       // B-blocks: 25 bx x 64 slices
#define NBLOCKS  2016

// ---------------- scratch (device globals; no allocation) ----------------
__device__ float  g_xp[2*TT*BB*HH];      // [dir][t][b][h]  -log2e * (input proj + biases)
__device__ float  g_totalH[TT*2*BB*HH];  // [t][dir][b][j]  coalesced for the rnn store
__device__ float  g_partial[VBLK*NROWS]; // per v-block partial sum-of-exp (deterministic)
__device__ float  g_rowstat[NROWS];      // log(sum exp) per row (natural log)
__device__ float  g_Wt1[16*VV];          // tiled tf32 W * log2e, 2 MB (single copy)
__device__ int    g_cnt[64];             // per slice: phase-A completion counters
__device__ int    g_flag[64];            // per slice: rowstat-ready flags
__device__ int    g_sliceCnt[64];        // per slice: rnn chain completion (16 = ready)
__device__ int    g_wflag[32];           // per bx: W region prepped
// pair-permuted tile layout: v-pair P = v>>4, u = v&15.
//   tile = 2P + ((u>>1)&1),  n = ((u>>2)<<1) | (u&1)
//   pos  = tile*128 + n*16 + (k&3)*4 + (k>>2)
// thread (g=n-group, q) owns 4 CONSECUTIVE v = P*16 + 4q + {0..3} -> STG.128.

// tf32 round (rna)
__device__ __forceinline__ unsigned tf32_of(float x) {
    unsigned r;
    asm("cvt.rna.tf32.f32 %0, %1;" : "=r"(r) : "f"(x));
    return r;
}
__device__ __forceinline__ float ex2(float x) {
    float r; asm("ex2.approx.f32 %0, %1;" : "=f"(r) : "f"(x)); return r;
}
__device__ __forceinline__ float rcp(float x) {
    float r; asm("rcp.approx.f32 %0, %1;" : "=f"(r) : "f"(x)); return r;
}

// m16n8k8 tf32 mma, D += A*B (C aliased to D)
__device__ __forceinline__ void mma_tf32(float& d0, float& d1, float& d2, float& d3,
                                         unsigned a0, unsigned a1, unsigned a2, unsigned a3,
                                         unsigned b0, unsigned b1) {
    asm("mma.sync.aligned.m16n8k8.row.col.f32.tf32.tf32.f32 "
        "{%0,%1,%2,%3}, {%4,%5,%6,%7}, {%8,%9}, {%0,%1,%2,%3};"
        : "+f"(d0), "+f"(d1), "+f"(d2), "+f"(d3)
        : "r"(a0), "r"(a1), "r"(a2), "r"(a3), "r"(b0), "r"(b1));
}

// readiness rank r (0..63) -> slice. Slice y ready at rnn step max(16y+15,1023-16y):
// middle slices earliest: 32,31,33,30,...,1,63, then 0 last.
__device__ __forceinline__ int rank_slice(int r) {
    if (r == 63) return 0;
    return (r & 1) ? (32 - ((r + 1) >> 1)) : (32 + (r >> 1));
}

// ---------------- kernel 1: embedding gather + x-projections + sync reset -----
__global__ void k_embed(const int* __restrict__ x, const float* __restrict__ emb,
                        const float* __restrict__ Wx1, const float* __restrict__ bx1,
                        const float* __restrict__ bh1,
                        const float* __restrict__ Wx2, const float* __restrict__ bx2,
                        const float* __restrict__ bh2) {
    int tid = blockIdx.x * blockDim.x + threadIdx.x;   // (t,b) flat
    if (blockIdx.x == 0 && threadIdx.x < 64) {         // reset sync state per replay
        g_cnt[threadIdx.x] = 0;
        g_flag[threadIdx.x] = 0;
        g_sliceCnt[threadIdx.x] = 0;
        if (threadIdx.x < 32) g_wflag[threadIdx.x] = 0;
    }
    if (tid >= NROWS) return;
    int idx = x[tid];
    const float4* em = (const float4*)(emb + (size_t)idx * EE);
    float e[EE];
    #pragma unroll
    for (int q = 0; q < 8; q++) {
        float4 v = __ldg(em + q);
        e[4*q] = v.x; e[4*q+1] = v.y; e[4*q+2] = v.z; e[4*q+3] = v.w;
    }
    #pragma unroll
    for (int j = 0; j < HH; j++) {
        float s1 = bx1[j] + bh1[j];
        float s2 = bx2[j] + bh2[j];
        #pragma unroll
        for (int k = 0; k < EE; k++) {
            s1 = fmaf(e[k], __ldg(Wx1 + k*HH + j), s1);
            s2 = fmaf(e[k], __ldg(Wx2 + k*HH + j), s2);
        }
        g_xp[tid*HH + j] = s1 * (-LOG2E);
        g_xp[TT*BB*HH + tid*HH + j] = s2 * (-LOG2E);
    }
}

// ---------------- rnn chain (carrier blocks) ----------------
// Threads 0..7; chain id c in 0..15. h exchange via double-buffered SMEM.
// Signals g_sliceCnt[t>>4] after finishing each 16-t slice (release).
__device__ void run_chain(int c, int j, float* sh,
                          const float* __restrict__ Wh1,
                          const float* __restrict__ Wh2) {
    int dir = c >> 3, b = c & 7;
    const float* Wh = dir ? Wh2 : Wh1;
    float w[HH];
    #pragma unroll
    for (int k = 0; k < HH; k++) w[k] = __ldg(Wh + k*HH + j) * (-LOG2E);

    const float* xp = g_xp + dir * (TT*BB*HH);
    float h = 0.f;

    float pf[4];
    #pragma unroll
    for (int p = 0; p < 4; p++) {
        int t = dir ? (TT - 1 - p) : p;
        pf[p] = __ldg(xp + (t*BB + b) * HH + j);
    }

    #pragma unroll 4
    for (int s = 0; s < TT; s++) {
        int slot = s & 3;
        float xv = pf[slot];
        if (s + 4 < TT) {
            int t4 = dir ? (TT - 1 - (s + 4)) : (s + 4);
            pf[slot] = __ldg(xp + (t4*BB + b) * HH + j);
        }
        int t = dir ? (TT - 1 - s) : s;
        g_totalH[t*128 + dir*64 + b*8 + j] = h;
        if ((t & 15) == (dir ? 0 : 15)) {
            __syncwarp(0xffu);
            __threadfence();                 // release totalH stores
            if (j == 0) atomicAdd(&g_sliceCnt[t >> 4], 1);
        }
        float* buf = sh + (s & 1) * 8;
        buf[j] = h;
        __syncwarp(0xffu);
        float4 lo = *(const float4*)(buf);
        float4 hi = *(const float4*)(buf + 4);
        float t0 = fmaf(lo.y, w[1], lo.x * w[0]);
        float t1 = fmaf(lo.w, w[3], lo.z * w[2]);
        float t2 = fmaf(hi.y, w[5], hi.x * w[4]);
        float t3 = fmaf(hi.w, w[7], hi.z * w[6]);
        float z  = xv + ((t0 + t1) + (t2 + t3));
        h = rcp(1.f + ex2(z));              // sigmoid
    }
}

// ---------------- fused kernel: role-split producer/consumer --------------------
// 1D grid, 2016 blocks, launch order = dependency order:
//  ids 0..15    : rnn carriers (exit after chains)
//  ids 16..415  : A-blocks — (bx, 4 cohorts in readiness order): sums->partials->
//                 stat by last-of-25 -> flag. Group-0 blocks also prep W[bx].
//  ids 416..2015: B-blocks — spin on flag[slice], then pure recompute+store.
// Producers never wait on consumers; all producers fit in wave 1
// (launch_bounds(256,3) => >=444 wave-1 slots >= 416).
__global__ __launch_bounds__(256, 3) void k_fused(float* __restrict__ out,
                                                  const float* __restrict__ Wo,
                                                  const float* __restrict__ Wh1,
                                                  const float* __restrict__ Wh2) {
    __shared__ __align__(16) float sh_h[16];
    __shared__ bool isLast;
    int id = blockIdx.x;

    // ================= carriers =================
    if (id < NCARRIER) {
        if (threadIdx.x < 8)
            run_chain(id, threadIdx.x, sh_h, Wh1, Wh2);
        return;
    }

    int lane = threadIdx.x & 31, w = threadIdx.x >> 5;
    int g = lane >> 2, q = lane & 3;

    // ================= A-blocks (producers) =================
    if (id < BBASE) {
        int a = id - ABASE;
        int bx = a % VBLK;
        int grp = a / VBLK;                 // 0..15 -> cohorts rank 4g..4g+3

        if (grp == 0) {
            // prep W region bx (pair-permuted tf32 * log2e)
            int vbase = bx * 1280;
            #pragma unroll 1
            for (int k = 0; k < 16; k++) {
                #pragma unroll
                for (int it = 0; it < 5; it++) {
                    int v = vbase + it * 256 + threadIdx.x;
                    float x = __ldg(Wo + (size_t)k * VV + v);
                    int P = v >> 4, u = v & 15;
                    int tile = 2*P + ((u >> 1) & 1);
                    int n = ((u >> 2) << 1) | (u & 1);
                    int pos = tile*128 + n*16 + (k & 3)*4 + (k >> 2);
                    g_Wt1[pos] = __uint_as_float(tf32_of(x * LOG2E));
                }
            }
            __threadfence();
            __syncthreads();
            if (threadIdx.x == 0) atomicExch(&g_wflag[bx], 1);
        } else {
            if (threadIdx.x == 0)
                while (atomicAdd(&g_wflag[bx], 0) == 0) __nanosleep(100);
            __syncthreads();
            __threadfence();
        }

        int vt0 = bx * (VITER * 16);
        const float4* Bbase = (const float4*)(g_Wt1 + (size_t)vt0 * 128 + g * 16 + q * 4);

        #pragma unroll 1
        for (int i = 0; i < 4; i++) {
            int y = rank_slice(grp * 4 + i);
            if (threadIdx.x == 0)
                while (atomicAdd(&g_sliceCnt[y], 0) < 16) __nanosleep(100);
            __syncthreads();
            __threadfence();               // acquire totalH[y]

            int rowBase = y * 128 + w * 16;
            unsigned ah[2][4];
            #pragma unroll
            for (int kt = 0; kt < 2; kt++) {
                #pragma unroll
                for (int jj = 0; jj < 4; jj++) {
                    int r = g + (jj & 1) * 8;
                    int k = kt * 8 + q + ((jj >> 1) ? 4 : 0);
                    int grow = rowBase + r, t = grow >> 3, b = grow & 7;
                    ah[kt][jj] = tf32_of(g_totalH[t*128 + (k >> 3)*64 + b*8 + (k & 7)]);
                }
            }

            float sum0 = 0.f, sum1 = 0.f;
            const float4* Bt = Bbase;
            for (int it = 0; it < VITER; it++) {
                #pragma unroll
                for (int pr = 0; pr < 8; pr++) {
                    float4 B0 = __ldg(Bt);
                    float4 B1 = __ldg(Bt + 32);
                    Bt += 64;
                    unsigned b000 = __float_as_uint(B0.x), b001 = __float_as_uint(B0.y);
                    unsigned b010 = __float_as_uint(B0.z), b011 = __float_as_uint(B0.w);
                    unsigned b100 = __float_as_uint(B1.x), b101 = __float_as_uint(B1.y);
                    unsigned b110 = __float_as_uint(B1.z), b111 = __float_as_uint(B1.w);

                    float e0 = 0.f, e1 = 0.f, e2 = 0.f, e3 = 0.f;
                    mma_tf32(e0,e1,e2,e3, ah[0][0],ah[0][1],ah[0][2],ah[0][3], b000,b001);
                    mma_tf32(e0,e1,e2,e3, ah[1][0],ah[1][1],ah[1][2],ah[1][3], b010,b011);
                    float f0 = 0.f, f1 = 0.f, f2 = 0.f, f3 = 0.f;
                    mma_tf32(f0,f1,f2,f3, ah[0][0],ah[0][1],ah[0][2],ah[0][3], b100,b101);
                    mma_tf32(f0,f1,f2,f3, ah[1][0],ah[1][1],ah[1][2],ah[1][3], b110,b111);

                    sum0 += (ex2(e0) + ex2(e1)) + (ex2(f0) + ex2(f1));
                    sum1 += (ex2(e2) + ex2(e3)) + (ex2(f2) + ex2(f3));
                }
            }
            sum0 += __shfl_xor_sync(0xffffffffu, sum0, 1);
            sum0 += __shfl_xor_sync(0xffffffffu, sum0, 2);
            sum1 += __shfl_xor_sync(0xffffffffu, sum1, 1);
            sum1 += __shfl_xor_sync(0xffffffffu, sum1, 2);
            if (q == 0) {
                float* p = g_partial + (size_t)bx * NROWS + rowBase;
                p[g    ] = sum0;
                p[g + 8] = sum1;
            }

            // stat by last-arriving A-unit of slice y
            __threadfence();               // publish partials (release)
            __syncthreads();
            if (threadIdx.x == 0) {
                int old = atomicAdd(&g_cnt[y], 1);
                isLast = (old == VBLK - 1);
            }
            __syncthreads();
            if (isLast) {
                int r0 = y * 128;
                for (int r = threadIdx.x; r < 128; r += 256) {
                    float s = 0.f;
                    #pragma unroll
                    for (int ii = 0; ii < VBLK; ii++)
                        s += __ldcg(g_partial + (size_t)ii * NROWS + r0 + r);
                    g_rowstat[r0 + r] = logf(s);
                }
                __threadfence();           // publish rowstat before flag
                __syncthreads();
                if (threadIdx.x == 0) atomicExch(&g_flag[y], 1);
            }
            __syncthreads();               // protect isLast reuse
        }
        return;
    }

    // ================= B-blocks (consumers) =================
    {
        int b = id - BBASE;
        int bx = b % VBLK;
        int y = rank_slice(b / VBLK);

        if (threadIdx.x == 0) {
            while (atomicAdd(&g_wflag[bx], 0) == 0) __nanosleep(200);
            while (atomicAdd(&g_flag[y], 0) == 0) __nanosleep(200);
        }
        __syncthreads();
        __threadfence();                   // acquire rowstat + totalH[y] + W

        int rowBase = y * 128 + w * 16;
        float st0 = __ldcg(g_rowstat + rowBase + g);
        float st1 = __ldcg(g_rowstat + rowBase + g + 8);

        unsigned ah[2][4];
        #pragma unroll
        for (int kt = 0; kt < 2; kt++) {
            #pragma unroll
            for (int jj = 0; jj < 4; jj++) {
                int r = g + (jj & 1) * 8;
                int k = kt * 8 + q + ((jj >> 1) ? 4 : 0);
                int grow = rowBase + r, t = grow >> 3, bb = grow & 7;
                ah[kt][jj] = tf32_of(g_totalH[t*128 + (k >> 3)*64 + bb*8 + (k & 7)]);
            }
        }

        int vt0 = bx * (VITER * 16);
        const float4* Bt = (const float4*)(g_Wt1 + (size_t)vt0 * 128 + g * 16 + q * 4);
        size_t vc = (size_t)vt0 * 8 + q * 4;
        float* op0 = out + (size_t)(rowBase + g    ) * VV + vc;
        float* op1 = out + (size_t)(rowBase + g + 8) * VV + vc;

        for (int it = 0; it < VITER; it++) {
            #pragma unroll
            for (int pr = 0; pr < 8; pr++) {
                float4 B0 = __ldg(Bt);
                float4 B1 = __ldg(Bt + 32);
                Bt += 64;
                unsigned b000 = __float_as_uint(B0.x), b001 = __float_as_uint(B0.y);
                unsigned b010 = __float_as_uint(B0.z), b011 = __float_as_uint(B0.w);
                unsigned b100 = __float_as_uint(B1.x), b101 = __float_as_uint(B1.y);
                unsigned b110 = __float_as_uint(B1.z), b111 = __float_as_uint(B1.w);

                float e0 = 0.f, e1 = 0.f, e2 = 0.f, e3 = 0.f;
                mma_tf32(e0,e1,e2,e3, ah[0][0],ah[0][1],ah[0][2],ah[0][3], b000,b001);
                mma_tf32(e0,e1,e2,e3, ah[1][0],ah[1][1],ah[1][2],ah[1][3], b010,b011);
                float f0 = 0.f, f1 = 0.f, f2 = 0.f, f3 = 0.f;
                mma_tf32(f0,f1,f2,f3, ah[0][0],ah[0][1],ah[0][2],ah[0][3], b100,b101);
                mma_tf32(f0,f1,f2,f3, ah[1][0],ah[1][1],ah[1][2],ah[1][3], b110,b111);

                float4 o0 = make_float4(fmaf(e0, LN2, -st0), fmaf(e1, LN2, -st0),
                                        fmaf(f0, LN2, -st0), fmaf(f1, LN2, -st0));
                float4 o1 = make_float4(fmaf(e2, LN2, -st1), fmaf(e3, LN2, -st1),
                                        fmaf(f2, LN2, -st1), fmaf(f3, LN2, -st1));
                __stcs((float4*)op0, o0);
                __stcs((float4*)op1, o1);
                op0 += 16; op1 += 16;
            }
        }
    }
}

// ---------------- launch ----------------
extern "C" void kernel_launch(void* const* d_in, const int* in_sizes, int n_in,
                              void* d_out, int out_size) {
    const int*   x   = (const int*)  d_in[0];
    const float* emb = (const float*)d_in[1];
    const float* Wx1 = (const float*)d_in[2];
    const float* bx1 = (const float*)d_in[3];
    const float* Wh1 = (const float*)d_in[4];
    const float* bh1 = (const float*)d_in[5];
    const float* Wx2 = (const float*)d_in[6];
    const float* bx2 = (const float*)d_in[7];
    const float* Wh2 = (const float*)d_in[8];
    const float* bh2 = (const float*)d_in[9];
    const float* Wo  = (const float*)d_in[10];
    float* out = (float*)d_out;

    k_embed<<<(NROWS + 255)/256, 256>>>(x, emb, Wx1, bx1, bh1, Wx2, bx2, bh2);
    k_fused<<<NBLOCKS, 256>>>(out, Wo, Wh1, Wh2);
}